// round 1
// baseline (speedup 1.0000x reference)
#include <cuda_runtime.h>
#include <cuda_bf16.h>

// ODECell: f = sigmoid(sigma*(in - mu)); fA = sum f*A; fs = sum f;
// x <- 6 Euler steps of dx = -omega*x + fA - x*fs, dt_u = 0.1/6.
//
// Inputs (metadata order):
//   d_in[0] inputs (2048*128 f32)
//   d_in[1] state  (2048*128 f32)
//   d_in[2] A      (128*128 f32)
//   d_in[3] sigma  (128*128 f32)
//   d_in[4] mu     (128*128 f32)
// Output: 2048*128 f32.

#define UNITS 128
#define IDIM  128
#define BATCH 2048
#define BB    2              // batches per block
#define OMEGA 0.1f
#define DT_U  (0.1f / 6.0f)
#define L2E   1.4426950408889634f

// Preprocessed, transposed weights: [d][u] layout for coalesced lane=u loads.
__device__ float g_sT[IDIM * UNITS];  // -log2(e) * sigma   (transposed)
__device__ float g_cT[IDIM * UNITS];  //  log2(e) * sigma*mu (transposed)
__device__ float g_AT[IDIM * UNITS];  //  A                  (transposed)

__device__ __forceinline__ float ex2f(float x) {
    float y; asm("ex2.approx.f32 %0, %1;" : "=f"(y) : "f"(x)); return y;
}
__device__ __forceinline__ float rcpf(float x) {
    float y; asm("rcp.approx.f32 %0, %1;" : "=f"(y) : "f"(x)); return y;
}

__global__ void ode_prep_kernel(const float* __restrict__ A,
                                const float* __restrict__ sigma,
                                const float* __restrict__ mu) {
    int i = blockIdx.x * blockDim.x + threadIdx.x;   // i = u*IDIM + d
    if (i < UNITS * IDIM) {
        int u = i / IDIM;
        int d = i % IDIM;
        float s = sigma[i];
        float m = mu[i];
        float a = A[i];
        g_sT[d * UNITS + u] = -L2E * s;
        g_cT[d * UNITS + u] =  L2E * s * m;
        g_AT[d * UNITS + u] = a;
    }
}

__global__ __launch_bounds__(UNITS, 8)
void ode_main_kernel(const float* __restrict__ inputs,
                     const float* __restrict__ state,
                     float* __restrict__ out) {
    const int u  = threadIdx.x;          // one unit per thread
    const int b0 = blockIdx.x * BB;      // first batch of this block

    __shared__ float s_in[BB][IDIM];
    #pragma unroll
    for (int k = 0; k < BB; ++k)
        s_in[k][u] = inputs[(b0 + k) * IDIM + u];   // blockDim == IDIM
    __syncthreads();

    float fA0 = 0.f, fs0 = 0.f;
    float fA1 = 0.f, fs1 = 0.f;

    #pragma unroll 4
    for (int d = 0; d < IDIM; ++d) {
        const int w = d * UNITS + u;
        float sT = __ldg(&g_sT[w]);
        float cT = __ldg(&g_cT[w]);
        float aT = __ldg(&g_AT[w]);
        float x0 = s_in[0][d];
        float x1 = s_in[1][d];

        // f = 1 / (1 + exp(-sigma*(x - mu))) = 1 / (1 + ex2(sT*x + cT))
        float e0 = ex2f(fmaf(sT, x0, cT));
        float f0 = rcpf(1.0f + e0);
        fA0 = fmaf(f0, aT, fA0);
        fs0 += f0;

        float e1 = ex2f(fmaf(sT, x1, cT));
        float f1 = rcpf(1.0f + e1);
        fA1 = fmaf(f1, aT, fA1);
        fs1 += f1;
    }

    // 6 Euler steps: x <- x*(1 - dt*(omega + fs)) + dt*fA
    {
        float a = 1.0f - DT_U * (OMEGA + fs0);
        float c = DT_U * fA0;
        float x = state[b0 * UNITS + u];
        #pragma unroll
        for (int k = 0; k < 6; ++k) x = fmaf(x, a, c);
        out[b0 * UNITS + u] = x;
    }
    {
        float a = 1.0f - DT_U * (OMEGA + fs1);
        float c = DT_U * fA1;
        float x = state[(b0 + 1) * UNITS + u];
        #pragma unroll
        for (int k = 0; k < 6; ++k) x = fmaf(x, a, c);
        out[(b0 + 1) * UNITS + u] = x;
    }
}

extern "C" void kernel_launch(void* const* d_in, const int* in_sizes, int n_in,
                              void* d_out, int out_size) {
    const float* inputs = (const float*)d_in[0];
    const float* state  = (const float*)d_in[1];
    const float* A      = (const float*)d_in[2];
    const float* sigma  = (const float*)d_in[3];
    const float* mu     = (const float*)d_in[4];
    float* out = (float*)d_out;

    ode_prep_kernel<<<(UNITS * IDIM + 255) / 256, 256>>>(A, sigma, mu);
    ode_main_kernel<<<BATCH / BB, UNITS>>>(inputs, state, out);
}

// round 2
// speedup vs baseline: 1.4443x; 1.4443x over previous
#include <cuda_runtime.h>
#include <cuda_bf16.h>

// ODECell: f = sigmoid(sigma*(in - mu)); fA = sum f*A; fs = sum f;
// x <- 6 Euler steps of dx = -omega*x + fA - x*fs, dt_u = 0.1/6.
//
// sigmoid(z) = 0.5 + 0.5*tanh(z/2)  -> one MUFU.TANH per element.
//   t = tanh(sH*x + cH), sH = 0.5*sigma, cH = -0.5*sigma*mu
//   fA = baseA[u] + sum_d t * AH,   AH = 0.5*A,  baseA = 0.5*sum_d A
//   fs = IDIM/2 + 0.5 * sum_d t
//
// Inputs: d_in[0] inputs(2048x128), d_in[1] state(2048x128),
//         d_in[2] A(128x128), d_in[3] sigma, d_in[4] mu. Output f32 2048x128.

#define UNITS 128
#define IDIM  128
#define BATCH 2048
#define BB    2
#define OMEGA 0.1f
#define DT_U  (0.1f / 6.0f)

// Transposed packed weights [d][u]: (sH, cH, AH, pad)
__device__ float4 g_w4[IDIM * UNITS];
__device__ float  g_baseA[UNITS];

__device__ __forceinline__ float tanhaf(float x) {
    float y; asm("tanh.approx.f32 %0, %1;" : "=f"(y) : "f"(x)); return y;
}

// One block per unit u (128 threads, one per d): pack weights + reduce baseA.
__global__ void ode_prep_kernel(const float* __restrict__ A,
                                const float* __restrict__ sigma,
                                const float* __restrict__ mu) {
    const int u = blockIdx.x;
    const int d = threadIdx.x;
    const int i = u * IDIM + d;

    float s  = sigma[i];
    float m  = mu[i];
    float a  = A[i];
    float ah = 0.5f * a;
    g_w4[d * UNITS + u] = make_float4(0.5f * s, -0.5f * s * m, ah, 0.0f);

    // block reduce sum(ah) -> g_baseA[u]
    __shared__ float red[4];
    float v = ah;
    #pragma unroll
    for (int off = 16; off > 0; off >>= 1)
        v += __shfl_down_sync(0xffffffffu, v, off);
    if ((d & 31) == 0) red[d >> 5] = v;
    __syncthreads();
    if (d == 0) g_baseA[u] = red[0] + red[1] + red[2] + red[3];
}

__global__ __launch_bounds__(UNITS)
void ode_main_kernel(const float* __restrict__ inputs,
                     const float* __restrict__ state,
                     float* __restrict__ out) {
    const int u  = threadIdx.x;
    const int b0 = blockIdx.x * BB;

    __shared__ float2 s_in[IDIM];   // (x of batch b0, x of batch b0+1) per d
    {
        float x0 = inputs[b0 * IDIM + u];
        float x1 = inputs[(b0 + 1) * IDIM + u];
        s_in[u] = make_float2(x0, x1);
    }
    __syncthreads();

    float acc0 = 0.f, st0 = 0.f;
    float acc1 = 0.f, st1 = 0.f;

    const float4* __restrict__ w = &g_w4[u];

    #pragma unroll 8
    for (int d = 0; d < IDIM; ++d) {
        float4 wv = __ldg(&w[d * UNITS]);   // LDG.128: sH, cH, AH
        float2 xi = s_in[d];                // LDS.64 broadcast

        float t0 = tanhaf(fmaf(wv.x, xi.x, wv.y));
        acc0 = fmaf(t0, wv.z, acc0);
        st0 += t0;

        float t1 = tanhaf(fmaf(wv.x, xi.y, wv.y));
        acc1 = fmaf(t1, wv.z, acc1);
        st1 += t1;
    }

    const float baseA = g_baseA[u];

    {
        float fA = baseA + acc0;
        float fs = (float)(IDIM / 2) + 0.5f * st0;
        float a  = 1.0f - DT_U * (OMEGA + fs);
        float c  = DT_U * fA;
        float x  = state[b0 * UNITS + u];
        #pragma unroll
        for (int k = 0; k < 6; ++k) x = fmaf(x, a, c);
        out[b0 * UNITS + u] = x;
    }
    {
        float fA = baseA + acc1;
        float fs = (float)(IDIM / 2) + 0.5f * st1;
        float a  = 1.0f - DT_U * (OMEGA + fs);
        float c  = DT_U * fA;
        float x  = state[(b0 + 1) * UNITS + u];
        #pragma unroll
        for (int k = 0; k < 6; ++k) x = fmaf(x, a, c);
        out[(b0 + 1) * UNITS + u] = x;
    }
}

extern "C" void kernel_launch(void* const* d_in, const int* in_sizes, int n_in,
                              void* d_out, int out_size) {
    const float* inputs = (const float*)d_in[0];
    const float* state  = (const float*)d_in[1];
    const float* A      = (const float*)d_in[2];
    const float* sigma  = (const float*)d_in[3];
    const float* mu     = (const float*)d_in[4];
    float* out = (float*)d_out;

    ode_prep_kernel<<<UNITS, IDIM>>>(A, sigma, mu);
    ode_main_kernel<<<BATCH / BB, UNITS>>>(inputs, state, out);
}

// round 4
// speedup vs baseline: 1.6224x; 1.1233x over previous
#include <cuda_runtime.h>
#include <cuda_fp16.h>

// ODECell: f = sigmoid(sigma*(in-mu)) = 0.5 + 0.5*tanh(0.5*sigma*(in-mu))
//   t = tanh(sH*x + cH)  with sH = 0.5*sigma (f16), cH = -0.5*sigma*mu (f16)
//   fA = baseA[u] + sum_d t * AH   (AH = 0.5*A, f32 accumulation)
//   fs = 64 + 0.5 * sum_d t
//   x <- 6 Euler steps of x*(1 - dt*(omega+fs)) + dt*fA
//
// f16x2 front-end: one MUFU.TANH per TWO d-elements. f32x2 packed FMA back-end.

#define UNITS 128
#define IDIM  128
#define DP    (IDIM / 2)     // 64 d-pairs
#define BATCH 2048
#define BB    2
#define OMEGA 0.1f
#define DT_U  (0.1f / 6.0f)

typedef unsigned int       u32;
typedef unsigned long long u64;

// Transposed packed weights [d_pair][u]: {sH2 bits, cH2 bits, AH0 bits, AH1 bits}
__device__ uint4 g_w[DP * UNITS];
__device__ float g_baseA[UNITS];

__device__ __forceinline__ u32 h2u(__half2 h) {
    u32 r; __builtin_memcpy(&r, &h, 4); return r;
}
__device__ __forceinline__ __half2 u2h(u32 u) {
    __half2 r; __builtin_memcpy(&r, &u, 4); return r;
}
__device__ __forceinline__ u32 tanh2u(u32 z) {
    u32 y; asm("tanh.approx.f16x2 %0, %1;" : "=r"(y) : "r"(z)); return y;
}
__device__ __forceinline__ u64 pack2(float lo, float hi) {
    u64 p;
    asm("mov.b64 %0, {%1, %2};" : "=l"(p)
        : "r"(__float_as_uint(lo)), "r"(__float_as_uint(hi)));
    return p;
}
__device__ __forceinline__ u64 fma2(u64 a, u64 b, u64 c) {
    u64 d; asm("fma.rn.f32x2 %0, %1, %2, %3;" : "=l"(d) : "l"(a), "l"(b), "l"(c));
    return d;
}
__device__ __forceinline__ u64 add2(u64 a, u64 b) {
    u64 d; asm("add.rn.f32x2 %0, %1, %2;" : "=l"(d) : "l"(a), "l"(b));
    return d;
}
__device__ __forceinline__ float2 unpack2(u64 p) {
    u32 lo, hi;
    asm("mov.b64 {%0, %1}, %2;" : "=r"(lo), "=r"(hi) : "l"(p));
    return make_float2(__uint_as_float(lo), __uint_as_float(hi));
}

// One block per unit u, 64 threads (one per d-pair): pack weights + reduce baseA.
__global__ void ode_prep_kernel(const float* __restrict__ A,
                                const float* __restrict__ sigma,
                                const float* __restrict__ mu) {
    const int u  = blockIdx.x;
    const int d2 = threadIdx.x;
    const int i  = u * IDIM + 2 * d2;

    float s0 = sigma[i],  s1 = sigma[i + 1];
    float m0 = mu[i],     m1 = mu[i + 1];
    float a0 = 0.5f * A[i], a1 = 0.5f * A[i + 1];

    __half2 sh2 = __halves2half2(__float2half_rn(0.5f * s0), __float2half_rn(0.5f * s1));
    __half2 ch2 = __halves2half2(__float2half_rn(-0.5f * s0 * m0),
                                 __float2half_rn(-0.5f * s1 * m1));

    uint4 w;
    w.x = h2u(sh2);
    w.y = h2u(ch2);
    w.z = __float_as_uint(a0);
    w.w = __float_as_uint(a1);
    g_w[d2 * UNITS + u] = w;

    // reduce sum(a0+a1) over 64 threads -> g_baseA[u]
    __shared__ float red[2];
    float v = a0 + a1;
    #pragma unroll
    for (int off = 16; off > 0; off >>= 1)
        v += __shfl_down_sync(0xffffffffu, v, off);
    if ((d2 & 31) == 0) red[d2 >> 5] = v;
    __syncthreads();
    if (d2 == 0) g_baseA[u] = red[0] + red[1];
}

__global__ __launch_bounds__(UNITS)
void ode_main_kernel(const float* __restrict__ inputs,
                     const float* __restrict__ state,
                     float* __restrict__ out) {
    const int u  = threadIdx.x;
    const int b0 = blockIdx.x * BB;

    // s_x[d2] = { half2(x_b0[2d2], x_b0[2d2+1]), half2(x_b1[...]) }
    __shared__ uint2 s_x[DP];
    if (u < DP) {
        const float2* in2 = (const float2*)inputs;
        float2 xa = in2[(b0 * IDIM) / 2 + u];
        float2 xb = in2[((b0 + 1) * IDIM) / 2 + u];
        uint2 p;
        p.x = h2u(__halves2half2(__float2half_rn(xa.x), __float2half_rn(xa.y)));
        p.y = h2u(__halves2half2(__float2half_rn(xb.x), __float2half_rn(xb.y)));
        s_x[u] = p;
    }
    __syncthreads();

    u64 acc0 = 0, st0 = 0;   // packed f32x2 accumulators (zero bits = {0,0})
    u64 acc1 = 0, st1 = 0;

    const uint4* __restrict__ w = &g_w[u];

    #pragma unroll 8
    for (int d2 = 0; d2 < DP; ++d2) {
        uint4 wv = __ldg(&w[d2 * UNITS]);   // LDG.128: sH2, cH2, AH0, AH1
        uint2 xp = s_x[d2];                 // LDS.64 broadcast

        u64 a2 = pack2(__uint_as_float(wv.z), __uint_as_float(wv.w));
        __half2 sh2 = u2h(wv.x), ch2 = u2h(wv.y);

        // batch 0
        {
            __half2 z = __hfma2(sh2, u2h(xp.x), ch2);
            __half2 t = u2h(tanh2u(h2u(z)));
            u64 tp = pack2(__low2float(t), __high2float(t));
            acc0 = fma2(tp, a2, acc0);
            st0  = add2(tp, st0);
        }
        // batch 1
        {
            __half2 z = __hfma2(sh2, u2h(xp.y), ch2);
            __half2 t = u2h(tanh2u(h2u(z)));
            u64 tp = pack2(__low2float(t), __high2float(t));
            acc1 = fma2(tp, a2, acc1);
            st1  = add2(tp, st1);
        }
    }

    const float baseA = g_baseA[u];

    {
        float2 a = unpack2(acc0), s = unpack2(st0);
        float fA = baseA + a.x + a.y;
        float fs = (float)(IDIM / 2) + 0.5f * (s.x + s.y);
        float am = 1.0f - DT_U * (OMEGA + fs);
        float c  = DT_U * fA;
        float x  = state[b0 * UNITS + u];
        #pragma unroll
        for (int k = 0; k < 6; ++k) x = fmaf(x, am, c);
        out[b0 * UNITS + u] = x;
    }
    {
        float2 a = unpack2(acc1), s = unpack2(st1);
        float fA = baseA + a.x + a.y;
        float fs = (float)(IDIM / 2) + 0.5f * (s.x + s.y);
        float am = 1.0f - DT_U * (OMEGA + fs);
        float c  = DT_U * fA;
        float x  = state[(b0 + 1) * UNITS + u];
        #pragma unroll
        for (int k = 0; k < 6; ++k) x = fmaf(x, am, c);
        out[(b0 + 1) * UNITS + u] = x;
    }
}

extern "C" void kernel_launch(void* const* d_in, const int* in_sizes, int n_in,
                              void* d_out, int out_size) {
    const float* inputs = (const float*)d_in[0];
    const float* state  = (const float*)d_in[1];
    const float* A      = (const float*)d_in[2];
    const float* sigma  = (const float*)d_in[3];
    const float* mu     = (const float*)d_in[4];
    float* out = (float*)d_out;

    ode_prep_kernel<<<UNITS, DP>>>(A, sigma, mu);
    ode_main_kernel<<<BATCH / BB, UNITS>>>(inputs, state, out);
}

// round 5
// speedup vs baseline: 1.8153x; 1.1189x over previous
#include <cuda_runtime.h>
#include <cuda_fp16.h>

// ODECell: f = sigmoid(sigma*(in-mu)) = 0.5 + 0.5*tanh(0.5*sigma*(in-mu))
//   t = tanh(sH*x + cH)  with sH = 0.5*sigma (f16), cH = -0.5*sigma*mu (f16)
//   fA = baseA[u] + sum_d t * AH   (AH = 0.5*A, f32 accumulation)
//   fs = 64 + 0.5 * sum_d t
//   x <- 6 Euler steps of x*(1 - dt*(omega+fs)) + dt*fA
//
// f16x2 front-end: one MUFU.TANH per TWO d-elements. f32x2 packed FMA back-end.
// R5: launch_bounds(128,8) -> 64-reg budget + full unroll for MLP~8.

#define UNITS 128
#define IDIM  128
#define DP    (IDIM / 2)     // 64 d-pairs
#define BATCH 2048
#define BB    2
#define OMEGA 0.1f
#define DT_U  (0.1f / 6.0f)

typedef unsigned int       u32;
typedef unsigned long long u64;

// Transposed packed weights [d_pair][u]: {sH2 bits, cH2 bits, AH0 bits, AH1 bits}
__device__ uint4 g_w[DP * UNITS];
__device__ float g_baseA[UNITS];

__device__ __forceinline__ u32 h2u(__half2 h) {
    u32 r; __builtin_memcpy(&r, &h, 4); return r;
}
__device__ __forceinline__ __half2 u2h(u32 u) {
    __half2 r; __builtin_memcpy(&r, &u, 4); return r;
}
__device__ __forceinline__ u32 tanh2u(u32 z) {
    u32 y; asm("tanh.approx.f16x2 %0, %1;" : "=r"(y) : "r"(z)); return y;
}
__device__ __forceinline__ u64 pack2(float lo, float hi) {
    u64 p;
    asm("mov.b64 %0, {%1, %2};" : "=l"(p)
        : "r"(__float_as_uint(lo)), "r"(__float_as_uint(hi)));
    return p;
}
__device__ __forceinline__ u64 fma2(u64 a, u64 b, u64 c) {
    u64 d; asm("fma.rn.f32x2 %0, %1, %2, %3;" : "=l"(d) : "l"(a), "l"(b), "l"(c));
    return d;
}
__device__ __forceinline__ u64 add2(u64 a, u64 b) {
    u64 d; asm("add.rn.f32x2 %0, %1, %2;" : "=l"(d) : "l"(a), "l"(b));
    return d;
}
__device__ __forceinline__ float2 unpack2(u64 p) {
    u32 lo, hi;
    asm("mov.b64 {%0, %1}, %2;" : "=r"(lo), "=r"(hi) : "l"(p));
    return make_float2(__uint_as_float(lo), __uint_as_float(hi));
}

// One block per unit u, 64 threads (one per d-pair): pack weights + reduce baseA.
__global__ void ode_prep_kernel(const float* __restrict__ A,
                                const float* __restrict__ sigma,
                                const float* __restrict__ mu) {
    const int u  = blockIdx.x;
    const int d2 = threadIdx.x;
    const int i  = u * IDIM + 2 * d2;

    float s0 = sigma[i],  s1 = sigma[i + 1];
    float m0 = mu[i],     m1 = mu[i + 1];
    float a0 = 0.5f * A[i], a1 = 0.5f * A[i + 1];

    __half2 sh2 = __halves2half2(__float2half_rn(0.5f * s0), __float2half_rn(0.5f * s1));
    __half2 ch2 = __halves2half2(__float2half_rn(-0.5f * s0 * m0),
                                 __float2half_rn(-0.5f * s1 * m1));

    uint4 w;
    w.x = h2u(sh2);
    w.y = h2u(ch2);
    w.z = __float_as_uint(a0);
    w.w = __float_as_uint(a1);
    g_w[d2 * UNITS + u] = w;

    __shared__ float red[2];
    float v = a0 + a1;
    #pragma unroll
    for (int off = 16; off > 0; off >>= 1)
        v += __shfl_down_sync(0xffffffffu, v, off);
    if ((d2 & 31) == 0) red[d2 >> 5] = v;
    __syncthreads();
    if (d2 == 0) g_baseA[u] = red[0] + red[1];
}

__global__ __launch_bounds__(UNITS, 8)   // 64-reg budget, 8 blocks/SM fits grid wave
void ode_main_kernel(const float* __restrict__ inputs,
                     const float* __restrict__ state,
                     float* __restrict__ out) {
    const int u  = threadIdx.x;
    const int b0 = blockIdx.x * BB;

    // s_x[d2] = { half2(x_b0[2d2], x_b0[2d2+1]), half2(x_b1[...]) }
    __shared__ uint2 s_x[DP];
    if (u < DP) {
        const float2* in2 = (const float2*)inputs;
        float2 xa = in2[(b0 * IDIM) / 2 + u];
        float2 xb = in2[((b0 + 1) * IDIM) / 2 + u];
        uint2 p;
        p.x = h2u(__halves2half2(__float2half_rn(xa.x), __float2half_rn(xa.y)));
        p.y = h2u(__halves2half2(__float2half_rn(xb.x), __float2half_rn(xb.y)));
        s_x[u] = p;
    }
    __syncthreads();

    u64 acc0 = 0, st0 = 0;   // packed f32x2 accumulators (zero bits = {0,0})
    u64 acc1 = 0, st1 = 0;

    const uint4* __restrict__ w = &g_w[u];

    #pragma unroll
    for (int d2 = 0; d2 < DP; ++d2) {
        uint4 wv = __ldg(&w[d2 * UNITS]);   // LDG.128: sH2, cH2, AH0, AH1
        uint2 xp = s_x[d2];                 // LDS.64 broadcast

        u64 a2 = pack2(__uint_as_float(wv.z), __uint_as_float(wv.w));
        __half2 sh2 = u2h(wv.x), ch2 = u2h(wv.y);

        // batch 0
        {
            __half2 z = __hfma2(sh2, u2h(xp.x), ch2);
            __half2 t = u2h(tanh2u(h2u(z)));
            u64 tp = pack2(__low2float(t), __high2float(t));
            acc0 = fma2(tp, a2, acc0);
            st0  = add2(tp, st0);
        }
        // batch 1
        {
            __half2 z = __hfma2(sh2, u2h(xp.y), ch2);
            __half2 t = u2h(tanh2u(h2u(z)));
            u64 tp = pack2(__low2float(t), __high2float(t));
            acc1 = fma2(tp, a2, acc1);
            st1  = add2(tp, st1);
        }
    }

    const float baseA = g_baseA[u];

    {
        float2 a = unpack2(acc0), s = unpack2(st0);
        float fA = baseA + a.x + a.y;
        float fs = (float)(IDIM / 2) + 0.5f * (s.x + s.y);
        float am = 1.0f - DT_U * (OMEGA + fs);
        float c  = DT_U * fA;
        float x  = state[b0 * UNITS + u];
        #pragma unroll
        for (int k = 0; k < 6; ++k) x = fmaf(x, am, c);
        out[b0 * UNITS + u] = x;
    }
    {
        float2 a = unpack2(acc1), s = unpack2(st1);
        float fA = baseA + a.x + a.y;
        float fs = (float)(IDIM / 2) + 0.5f * (s.x + s.y);
        float am = 1.0f - DT_U * (OMEGA + fs);
        float c  = DT_U * fA;
        float x  = state[(b0 + 1) * UNITS + u];
        #pragma unroll
        for (int k = 0; k < 6; ++k) x = fmaf(x, am, c);
        out[(b0 + 1) * UNITS + u] = x;
    }
}

extern "C" void kernel_launch(void* const* d_in, const int* in_sizes, int n_in,
                              void* d_out, int out_size) {
    const float* inputs = (const float*)d_in[0];
    const float* state  = (const float*)d_in[1];
    const float* A      = (const float*)d_in[2];
    const float* sigma  = (const float*)d_in[3];
    const float* mu     = (const float*)d_in[4];
    float* out = (float*)d_out;

    ode_prep_kernel<<<UNITS, DP>>>(A, sigma, mu);
    ode_main_kernel<<<BATCH / BB, UNITS>>>(inputs, state, out);
}